// round 15
// baseline (speedup 1.0000x reference)
#include <cuda_runtime.h>

// CTC batch cost, linear-domain forward. v9: TWO batch items per warp,
// instruction-interleaved. Each item's shfl/load latency is hidden by the
// other item's compute (the kernel was single-warp-latency-bound: 1 warp per
// SMSP, nothing else to issue during stalls). 8-slot register ring per item,
// L2 prefetch 3 periods ahead, off-chain per-lane exact power-of-2 renorm.
// Lane l owns states 4l..4l+3 of both items.

#define Bc 256
#define Tc 512
#define Cc 128
#define Uc 48
#define BLANKC 127
#define FULLM 0xffffffffu
#define EBIAS 207          // 127 + 80: renorm target exponent 2^80
#define RING 8

__device__ __forceinline__ float lg2f_(float x) {
    float y; asm("lg2.approx.f32 %0, %1;" : "=f"(y) : "f"(x)); return y;
}
__device__ __forceinline__ int iclamp(int v, int lo, int hi) {
    return v < lo ? lo : (v > hi ? hi : v);
}
__device__ __forceinline__ float p2f(int e) {      // exact 2^e, e in [-126,126]
    return __int_as_float((unsigned)(127 + e) << 23);
}

// One timestep of item I. Consumes pa##I (prev step's shfl), issues next early.
#define STEP_I(I, PB_, PL0_, PL1_, SCL_, SK1S_) do {                         \
    float a01_ = a##I##0 + a##I##1;                                          \
    float a23_ = a##I##2 + a##I##3;                                          \
    float a12_ = a##I##1 + a##I##2;                                          \
    float n3_ = fmaf(sk3##I, a##I##1, a23_) * (PL1_);                        \
    float pa3n_ = __shfl_up_sync(FULLM, n3_, 1);                             \
    float n2_ = a12_ * (PB_);                                                \
    float n1_ = fmaf((SK1S_), pa##I, a01_) * (PL0_);                         \
    float n0_ = fmaf((SCL_), pa##I, a##I##0) * (PB_);                        \
    a##I##0 = n0_; a##I##1 = n1_; a##I##2 = n2_; a##I##3 = n3_;              \
    pa##I = pa3n_;                                                           \
} while (0)

// Off-chain renorm decision for item I (applied later at period end).
#define RENORM_DEC(I) do {                                                   \
    float m_ = fmaxf(fmaxf(a##I##0, a##I##1), fmaxf(a##I##2, a##I##3));      \
    bool alive_ = (m_ > 0.f);                                                \
    int e_ = ((__float_as_int(m_) >> 23) & 0xff) - EBIAS;                    \
    e_ = iclamp(e_, -126, 126);                                              \
    int cand_ = eacc##I + e_;                                                \
    int adopt_ = __reduce_min_sync(FULLM, alive_ ? cand_ : 0x7fffffff);      \
    int eaccN_ = alive_ ? cand_ : adopt_;                                    \
    int dsc_ = alive_ ? -e_ : (eacc##I - adopt_);                            \
    sc_p##I = p2f(iclamp(dsc_, -126, 126));                                  \
    int eLold_ = __shfl_up_sync(FULLM, eacc##I, 1);                          \
    int eLnew_ = __shfl_up_sync(FULLM, eaccN_, 1);                           \
    int de0_ = eLold_ - eaccN_;                                              \
    int de_  = eLnew_ - eaccN_;                                              \
    scL0n##I = (lane == 0 || de0_ < -126) ? 0.f                              \
                                          : p2f(iclamp(de0_, -126, 126));    \
    scLn##I  = (lane == 0 || de_  < -126) ? 0.f                              \
                                          : p2f(iclamp(de_,  -126, 126));    \
    eacc_p##I = eaccN_;                                                      \
} while (0)

#define RENORM_APPLY(I) do {                                                 \
    a##I##0 *= sc_p##I; a##I##1 *= sc_p##I;                                  \
    a##I##2 *= sc_p##I; a##I##3 *= sc_p##I;                                  \
    eacc##I = eacc_p##I;                                                     \
    scL##I = scLn##I; scL0##I = scL0n##I;                                    \
    sk1s##I = sk1##I * scL##I; sk1s0##I = sk1##I * scL0##I;                  \
} while (0)

__global__ __launch_bounds__(64)
void ctc_lin9_kernel(const void* __restrict__ yt_raw,
                     const float* __restrict__ y_pred,
                     float* __restrict__ out)
{
    const int lane = threadIdx.x & 31;
    const int w    = threadIdx.x >> 5;
    const int gw   = blockIdx.x * 2 + w;     // global warp id, 0..127
    const int bA   = gw * 2;                 // this warp's two batch items
    const int bB   = gw * 2 + 1;

    // ---- label dtype probe (int64 vs int32), deterministic ----
    const long long* q64 = (const long long*)yt_raw;
    long long v0 = q64[lane * 2], v1 = q64[lane * 2 + 1];
    bool inr = (v0 >= 0 && v0 <= 127 && v1 >= 0 && v1 <= 127);
    bool is64 = __all_sync(FULLM, inr);
    const int* q32 = (const int*)yt_raw;

    // ---- per-lane labels + skip flags (per item) ----
    int u0 = 2 * lane, u1 = 2 * lane + 1;
    int cu0 = (u0 < Uc) ? u0 : 0;
    int cu1 = (u1 < Uc) ? u1 : 0;
    int l0A = is64 ? (int)q64[bA * Uc + cu0] : q32[bA * Uc + cu0];
    int l1A = is64 ? (int)q64[bA * Uc + cu1] : q32[bA * Uc + cu1];
    int l0B = is64 ? (int)q64[bB * Uc + cu0] : q32[bB * Uc + cu0];
    int l1B = is64 ? (int)q64[bB * Uc + cu1] : q32[bB * Uc + cu1];
    int lpA = __shfl_up_sync(FULLM, l1A, 1);
    int lpB = __shfl_up_sync(FULLM, l1B, 1);
    float sk1A = (u0 == 0 || l0A != lpA) ? 1.f : 0.f;
    float sk3A = (l1A != l0A) ? 1.f : 0.f;
    float sk1B = (u0 == 0 || l0B != lpB) ? 1.f : 0.f;
    float sk3B = (l1B != l0B) ? 1.f : 0.f;

    const float* baseA = y_pred + (size_t)bA * Tc * Cc;
    const float* baseB = y_pred + (size_t)bB * Tc * Cc;
    const float* qbA = baseA + BLANKC;
    const float* q0A = baseA + l0A;
    const float* q1A = baseA + l1A;
    const float* qbB = baseB + BLANKC;
    const float* q0B = baseB + l0B;
    const float* q1B = baseB + l1B;

    // ---- t = 0 init ----
    float aA0 = (lane == 0) ? qbA[0] : 0.f;
    float aA1 = (lane == 0) ? q0A[0] : 0.f;
    float aA2 = 0.f, aA3 = 0.f, paA = 0.f;
    float aB0 = (lane == 0) ? qbB[0] : 0.f;
    float aB1 = (lane == 0) ? q0B[0] : 0.f;
    float aB2 = 0.f, aB3 = 0.f, paB = 0.f;
    int   eaccA = 0, eaccB = 0;
    float scLA  = (lane == 0) ? 0.f : 1.f;
    float scLB  = scLA;
    float scL0A = scLA, scL0B = scLA;
    float sk1sA = sk1A * scLA, sk1s0A = sk1sA;
    float sk1sB = sk1B * scLB, sk1s0B = sk1sB;

    // ---- L2 prefetch rows t=1..24 for both items (3 periods ahead) ----
    for (int pp = 0; pp < 3; pp++) {
        int tf = 1 + pp * 8 + (lane >> 2);
        const float* pfA = baseA + (size_t)tf * Cc + (lane & 3) * 32;
        const float* pfB = baseB + (size_t)tf * Cc + (lane & 3) * 32;
        asm volatile("prefetch.global.L2 [%0];" :: "l"(pfA));
        asm volatile("prefetch.global.L2 [%0];" :: "l"(pfB));
    }

    // ---- 8-slot register rings, prefill rows t = 1..8 ----
    float rbA[RING], r0A[RING], r1A[RING];
    float rbB[RING], r0B[RING], r1B[RING];
#pragma unroll
    for (int j = 0; j < RING; j++) {
        rbA[j] = qbA[(1 + j) * Cc]; r0A[j] = q0A[(1 + j) * Cc]; r1A[j] = q1A[(1 + j) * Cc];
        rbB[j] = qbB[(1 + j) * Cc]; r0B[j] = q0B[(1 + j) * Cc]; r1B[j] = q1B[(1 + j) * Cc];
    }

    // pending renorm state
    float sc_pA = 1.f, scLnA = scLA, scL0nA = scLA; int eacc_pA = 0;
    float sc_pB = 1.f, scLnB = scLB, scL0nB = scLB; int eacc_pB = 0;

    // ---- main loop: periods k = 0..62 cover t = 1..504 ----
    const float* pbkA = qbA; const float* p0kA = q0A; const float* p1kA = q1A;
    const float* pbkB = qbB; const float* p0kB = q0B; const float* p1kB = q1B;
    for (int k = 0; k < 63; k++) {
        const bool v7 = (k <= 61);     // refill row 8k+16 valid (j==7)

#pragma unroll
        for (int j = 0; j < 8; j++) {
            float pbA_  = rbA[j], pl0A_ = r0A[j], pl1A_ = r1A[j];
            float pbB_  = rbB[j], pl0B_ = r0B[j], pl1B_ = r1B[j];
            if (j == 0) {
                STEP_I(A, pbA_, pl0A_, pl1A_, scL0A, sk1s0A);
                STEP_I(B, pbB_, pl0B_, pl1B_, scL0B, sk1s0B);
            } else {
                STEP_I(A, pbA_, pl0A_, pl1A_, scLA, sk1sA);
                STEP_I(B, pbB_, pl0B_, pl1B_, scLB, sk1sB);
            }
            // refill slot j with row 8k+9+j (consumed next period, 8 steps on)
            if (j <= 6 || v7) {
                rbA[j] = pbkA[(9 + j) * Cc];
                r0A[j] = p0kA[(9 + j) * Cc];
                r1A[j] = p1kA[(9 + j) * Cc];
                rbB[j] = pbkB[(9 + j) * Cc];
                r0B[j] = p0kB[(9 + j) * Cc];
                r1B[j] = p1kB[(9 + j) * Cc];
            }
            if (j == 2) {   // L2 prefetch: period k+3 rows, item A
                int tf = 8 * k + 25 + (lane >> 2);
                if (tf > Tc - 1) tf = Tc - 1;
                const float* pf = baseA + (size_t)tf * Cc + (lane & 3) * 32;
                asm volatile("prefetch.global.L2 [%0];" :: "l"(pf));
            }
            if (j == 3) {   // L2 prefetch: period k+3 rows, item B
                int tf = 8 * k + 25 + (lane >> 2);
                if (tf > Tc - 1) tf = Tc - 1;
                const float* pf = baseB + (size_t)tf * Cc + (lane & 3) * 32;
                asm volatile("prefetch.global.L2 [%0];" :: "l"(pf));
            }
            if (j == 4) RENORM_DEC(A);
            if (j == 5) RENORM_DEC(B);
        }
        RENORM_APPLY(A);
        RENORM_APPLY(B);
        pbkA += 8 * Cc; p0kA += 8 * Cc; p1kA += 8 * Cc;
        pbkB += 8 * Cc; p0kB += 8 * Cc; p1kB += 8 * Cc;
    }

    // ---- epilogue: t = 505..511 (slots 0..6 hold them), no renorm ----
#pragma unroll
    for (int j = 0; j < 7; j++) {
        if (j == 0) {
            STEP_I(A, rbA[0], r0A[0], r1A[0], scL0A, sk1s0A);
            STEP_I(B, rbB[0], r0B[0], r1B[0], scL0B, sk1s0B);
        } else {
            STEP_I(A, rbA[j], r0A[j], r1A[j], scLA, sk1sA);
            STEP_I(B, rbB[j], r0B[j], r1B[j], scLB, sk1sB);
        }
    }

    // ---- finish: states 95 (lane23,a3) and 96 (lane24,a0) per item ----
    float v95A = __shfl_sync(FULLM, aA3, 23); int e95A = __shfl_sync(FULLM, eaccA, 23);
    float v96A = __shfl_sync(FULLM, aA0, 24); int e96A = __shfl_sync(FULLM, eaccA, 24);
    float v95B = __shfl_sync(FULLM, aB3, 23); int e95B = __shfl_sync(FULLM, eaccB, 23);
    float v96B = __shfl_sync(FULLM, aB0, 24); int e96B = __shfl_sync(FULLM, eaccB, 24);
    if (lane == 0) {
        int emA = e95A > e96A ? e95A : e96A;
        float sA = ldexpf(v95A, e95A - emA) + ldexpf(v96A, e96A - emA);
        out[bA] = -(lg2f_(sA) + (float)emA) * 0.69314718055994530942f;
        int emB = e95B > e96B ? e95B : e96B;
        float sB = ldexpf(v95B, e95B - emB) + ldexpf(v96B, e96B - emB);
        out[bB] = -(lg2f_(sB) + (float)emB) * 0.69314718055994530942f;
    }
}

extern "C" void kernel_launch(void* const* d_in, const int* in_sizes, int n_in,
                              void* d_out, int out_size)
{
    (void)in_sizes; (void)n_in; (void)out_size;
    const void*  y_true = d_in[0];
    const float* y_pred = (const float*)d_in[1];
    float* out = (float*)d_out;
    ctc_lin9_kernel<<<Bc / 4, 64>>>(y_true, y_pred, out);
}

// round 16
// speedup vs baseline: 1.5042x; 1.5042x over previous
#include <cuda_runtime.h>

// CTC batch cost, linear-domain forward. v10 = v3 (best, 19.2us) with a
// 6-stage cp.async pipeline (prefetch distance ~1000cyc >> DRAM latency) and
// one warp per CTA. Group-tracked completion (no scoreboard aliasing), probs
// pre-gathered into registers one period ahead, pipelined shfl, off-chain
// per-lane exact power-of-2 renorm (decision @ j==5, bias 2^80).
// One warp per batch item; lane l owns states 4l..4l+3.

#define Bc 256
#define Tc 512
#define Cc 128
#define Uc 48
#define BLANKC 127
#define FULLM 0xffffffffu
#define EBIAS 207          // 127 + 80: renorm target exponent 2^80
#define NBUF 6

__device__ __forceinline__ float lg2f_(float x) {
    float y; asm("lg2.approx.f32 %0, %1;" : "=f"(y) : "f"(x)); return y;
}
__device__ __forceinline__ unsigned smem_u32(const void* p) {
    unsigned a;
    asm("{ .reg .u64 t; cvta.to.shared.u64 t, %1; cvt.u32.u64 %0, t; }"
        : "=r"(a) : "l"(p));
    return a;
}
__device__ __forceinline__ void cpa16(unsigned dst, const void* src) {
    asm volatile("cp.async.cg.shared.global [%0], [%1], 16;"
                 :: "r"(dst), "l"(src) : "memory");
}
__device__ __forceinline__ void cpcommit() {
    asm volatile("cp.async.commit_group;" ::: "memory");
}
__device__ __forceinline__ void cpwait4() {
    asm volatile("cp.async.wait_group 4;" ::: "memory");
}
__device__ __forceinline__ int iclamp(int v, int lo, int hi) {
    return v < lo ? lo : (v > hi ? hi : v);
}
__device__ __forceinline__ float p2f(int e) {      // exact 2^e, e in [-126,126]
    return __int_as_float((unsigned)(127 + e) << 23);
}

// One timestep. Consumes pa3 (prev step's shfl result), issues next shfl early.
#define STEP(PB_, PL0_, PL1_, SCL_, SK1S_) do {                              \
    float a01 = a0 + a1;                                                     \
    float a23 = a2 + a3;                                                     \
    float a12 = a1 + a2;                                                     \
    float n3 = fmaf(sk3, a1, a23) * (PL1_);                                  \
    float pa3n = __shfl_up_sync(FULLM, n3, 1);                               \
    float n2 = a12 * (PB_);                                                  \
    float n1 = fmaf((SK1S_), pa3, a01) * (PL0_);                             \
    float n0 = fmaf((SCL_), pa3, a0) * (PB_);                                \
    a0 = n0; a1 = n1; a2 = n2; a3 = n3; pa3 = pa3n;                          \
} while (0)

__global__ __launch_bounds__(32)
void ctc_lin10_kernel(const void* __restrict__ yt_raw,
                      const float* __restrict__ y_pred,
                      float* __restrict__ out)
{
    __shared__ __align__(128) float rows[NBUF][8][Cc];   // 24 KB

    const int lane = threadIdx.x & 31;
    const int b    = blockIdx.x;

    // ---- label dtype probe (int64 vs int32), deterministic ----
    const long long* q64 = (const long long*)yt_raw;
    long long v0 = q64[lane * 2], v1 = q64[lane * 2 + 1];
    bool inr = (v0 >= 0 && v0 <= 127 && v1 >= 0 && v1 <= 127);
    bool is64 = __all_sync(FULLM, inr);
    const int* q32 = (const int*)yt_raw;

    // ---- per-lane labels + skip flags ----
    int u0 = 2 * lane, u1 = 2 * lane + 1;
    int cu0 = (u0 < Uc) ? u0 : 0;
    int cu1 = (u1 < Uc) ? u1 : 0;
    int l0 = is64 ? (int)q64[b * Uc + cu0] : q32[b * Uc + cu0];
    int l1 = is64 ? (int)q64[b * Uc + cu1] : q32[b * Uc + cu1];
    int lprev = __shfl_up_sync(FULLM, l1, 1);
    float sk1 = (u0 == 0 || l0 != lprev) ? 1.f : 0.f;
    float sk3 = (l1 != l0) ? 1.f : 0.f;

    const float* base = y_pred + (size_t)b * Tc * Cc;
    const unsigned sb = smem_u32(&rows[0][0][0]);

    // ---- t = 0 init ----
    float a0 = (lane == 0) ? base[BLANKC] : 0.f;
    float a1 = (lane == 0) ? base[l0] : 0.f;
    float a2 = 0.f, a3 = 0.f, pa3 = 0.f;
    int   eacc = 0;
    float scL  = (lane == 0) ? 0.f : 1.f;
    float scL0 = scL;
    float sk1s = sk1 * scL, sk1s0 = sk1s;

    // ---- prefill periods 0..5 (rows t = 1..48), 6 groups ----
    for (int p = 0; p < NBUF; p++) {
        for (int j = 0; j < 8; j++) {
            int t = 1 + 8 * p + j;
            cpa16(sb + (unsigned)(((p * 8 + j) * Cc) * 4 + lane * 16),
                  base + (size_t)t * Cc + lane * 4);
        }
        cpcommit();
    }
    cpwait4();          // periods 0,1 resident
    __syncwarp();

    // ---- pre-gather period 0 probs into registers ----
    float Pb[8], P0[8], P1[8];
    {
        const float* r = &rows[0][0][0];
#pragma unroll
        for (int j = 0; j < 8; j++) {
            Pb[j] = r[j * Cc + BLANKC];
            P0[j] = r[j * Cc + l0];
            P1[j] = r[j * Cc + l1];
        }
    }

    // pending renorm state (computed @ j==5, applied at period end)
    float sc_p = 1.f, scLn = scL, scL0n = scL;
    int   eacc_p = 0;

    // ---- main loop: periods k = 0..62 cover t = 1..504 ----
    for (int k = 0; k < 63; k++) {
#pragma unroll
        for (int j = 0; j < 8; j++) {
            if (j == 0) STEP(Pb[0], P0[0], P1[0], scL0, sk1s0);
            else        STEP(Pb[j], P0[j], P1[j], scL,  sk1s);

            if (j == 5) {                     // off-chain renorm decision
                float m5 = fmaxf(fmaxf(a0, a1), fmaxf(a2, a3));
                bool alive = (m5 > 0.f);
                int e = ((__float_as_int(m5) >> 23) & 0xff) - EBIAS;
                e = iclamp(e, -126, 126);
                int cand = eacc + e;
                int adopt = __reduce_min_sync(FULLM, alive ? cand : 0x7fffffff);
                int eaccN = alive ? cand : adopt;
                int dsc = alive ? -e : (eacc - adopt);
                sc_p = p2f(iclamp(dsc, -126, 126));
                int eLold = __shfl_up_sync(FULLM, eacc, 1);
                int eLnew = __shfl_up_sync(FULLM, eaccN, 1);
                int de0 = eLold - eaccN;
                int de  = eLnew - eaccN;
                scL0n = (lane == 0 || de0 < -126) ? 0.f : p2f(iclamp(de0, -126, 126));
                scLn  = (lane == 0 || de  < -126) ? 0.f : p2f(iclamp(de,  -126, 126));
                eacc_p = eaccN;
            }
        }

        // issue loads for period k+6 into buf k%6 (its data was harvested
        // into registers at the end of period k-1; smem contents are dead)
        if (k <= 57) {
            unsigned dstb = sb + (unsigned)((k % NBUF) * 8 * Cc * 4 + lane * 16);
            for (int j = 0; j < 8; j++) {
                int t = 8 * (k + 6) + 1 + j;
                if (t > Tc - 1) t = Tc - 1;   // only period 63 slot 7 clamps
                cpa16(dstb + (unsigned)(j * Cc * 4),
                      base + (size_t)t * Cc + lane * 4);
            }
        }
        cpcommit();                            // one group per period (may be empty)
        cpwait4();                             // period k+1 resident (4 newest pending)
        __syncwarp();

        // ---- apply pending renorm (exact power-of-2, error-free) ----
        a0 *= sc_p; a1 *= sc_p; a2 *= sc_p; a3 *= sc_p;
        eacc = eacc_p;
        scL = scLn; scL0 = scL0n;
        sk1s = sk1 * scL; sk1s0 = sk1 * scL0;

        // ---- pre-gather period k+1 probs ----
        {
            const float* r = &rows[(k + 1) % NBUF][0][0];
#pragma unroll
            for (int j = 0; j < 8; j++) {
                Pb[j] = r[j * Cc + BLANKC];
                P0[j] = r[j * Cc + l0];
                P1[j] = r[j * Cc + l1];
            }
        }
    }

    // ---- epilogue: period 63, t = 505..511 (7 steps), no renorm ----
#pragma unroll
    for (int j = 0; j < 7; j++) {
        if (j == 0) STEP(Pb[0], P0[0], P1[0], scL0, sk1s0);
        else        STEP(Pb[j], P0[j], P1[j], scL,  sk1s);
    }

    // ---- finish: true = stored * 2^eacc; states 95 (lane23,a3), 96 (lane24,a0)
    float v95 = __shfl_sync(FULLM, a3, 23); int e95 = __shfl_sync(FULLM, eacc, 23);
    float v96 = __shfl_sync(FULLM, a0, 24); int e96 = __shfl_sync(FULLM, eacc, 24);
    if (lane == 0) {
        int em = e95 > e96 ? e95 : e96;
        float s = ldexpf(v95, e95 - em) + ldexpf(v96, e96 - em);
        float ll2 = lg2f_(s) + (float)em;
        out[b] = -ll2 * 0.69314718055994530942f;
    }
}

extern "C" void kernel_launch(void* const* d_in, const int* in_sizes, int n_in,
                              void* d_out, int out_size)
{
    (void)in_sizes; (void)n_in; (void)out_size;
    const void*  y_true = d_in[0];
    const float* y_pred = (const float*)d_in[1];
    float* out = (float*)d_out;
    ctc_lin10_kernel<<<Bc, 32>>>(y_true, y_pred, out);
}